// round 1
// baseline (speedup 1.0000x reference)
#include <cuda_runtime.h>
#include <cuda_bf16.h>

// out[b] = sum_k x[b,k] * |W[k]| * fc1_w[k] + fc1_b
// B=32, K = T*P = 4,000,000
#define NBATCH 32
#define TP     4000000
#define NVEC   (TP / 4)   // 1,000,000 float4 per batch row

__global__ void init_out_kernel(const float* __restrict__ fc1_b,
                                float* __restrict__ out) {
    out[threadIdx.x] = fc1_b[0];
}

__global__ __launch_bounds__(256)
void dot_kernel(const float4* __restrict__ x,
                const float4* __restrict__ W,
                const float4* __restrict__ F,
                float* __restrict__ out) {
    // Packed f32x2 accumulators: acc[b] holds (sum_even, sum_odd) for batch b.
    unsigned long long acc[NBATCH];
#pragma unroll
    for (int b = 0; b < NBATCH; b++) acc[b] = 0ULL;

    const int stride = gridDim.x * blockDim.x;
    const ulonglong2* __restrict__ xq = reinterpret_cast<const ulonglong2*>(x);

#pragma unroll 4
    for (int i = blockIdx.x * blockDim.x + threadIdx.x; i < NVEC; i += stride) {
        float4 w = W[i];
        float4 f = F[i];
        float c0 = fabsf(w.x) * f.x;
        float c1 = fabsf(w.y) * f.y;
        float c2 = fabsf(w.z) * f.z;
        float c3 = fabsf(w.w) * f.w;
        unsigned long long c01, c23;
        asm("mov.b64 %0, {%1,%2};" : "=l"(c01) : "f"(c0), "f"(c1));
        asm("mov.b64 %0, {%1,%2};" : "=l"(c23) : "f"(c2), "f"(c3));
#pragma unroll
        for (int b = 0; b < NBATCH; b++) {
            // 16B load: (x0,x1) in .x, (x2,x3) in .y — already f32x2-packed.
            ulonglong2 xv = xq[(size_t)b * NVEC + i];
            asm("fma.rn.f32x2 %0, %1, %2, %0;" : "+l"(acc[b]) : "l"(xv.x), "l"(c01));
            asm("fma.rn.f32x2 %0, %1, %2, %0;" : "+l"(acc[b]) : "l"(xv.y), "l"(c23));
        }
    }

    // ---- reduction: warp shfl -> smem cross-warp -> atomicAdd ----
    __shared__ float sred[8][NBATCH];
    const int lane = threadIdx.x & 31;
    const int wrp  = threadIdx.x >> 5;

#pragma unroll
    for (int b = 0; b < NBATCH; b++) {
        float lo, hi;
        asm("mov.b64 {%0,%1}, %2;" : "=f"(lo), "=f"(hi) : "l"(acc[b]));
        float v = lo + hi;
#pragma unroll
        for (int off = 16; off; off >>= 1)
            v += __shfl_xor_sync(0xffffffffu, v, off);
        if (lane == 0) sred[wrp][b] = v;
    }
    __syncthreads();

    if (wrp == 0) {
        const int nw = blockDim.x >> 5;
        float v = 0.0f;
#pragma unroll
        for (int w2 = 0; w2 < 8; w2++)
            if (w2 < nw) v += sred[w2][lane];
        atomicAdd(&out[lane], v);
    }
}

extern "C" void kernel_launch(void* const* d_in, const int* in_sizes, int n_in,
                              void* d_out, int out_size) {
    const float4* x  = (const float4*)d_in[0];  // [32, 4M]
    const float4* W  = (const float4*)d_in[1];  // [4M]
    const float4* F  = (const float4*)d_in[2];  // fc1_w [4M]
    const float*  bb = (const float*)d_in[3];   // fc1_b [1]
    float* out = (float*)d_out;                 // [32]

    (void)in_sizes; (void)n_in; (void)out_size;

    // Reset output each launch (graph-replay idempotent), then accumulate.
    init_out_kernel<<<1, NBATCH>>>(bb, out);

    const int threads = 256;
    const int blocks  = 296;   // 2 per SM; grid-stride covers NVEC
    dot_kernel<<<blocks, threads>>>(x, W, F, out);
}

// round 2
// speedup vs baseline: 1.1694x; 1.1694x over previous
#include <cuda_runtime.h>
#include <cuda_bf16.h>

// out[b] = sum_k x[b,k] * |W[k]| * fc1_w[k] + fc1_b
// B=32, K = T*P = 4,000,000
#define NBATCH  32
#define TP      4000000
#define NVEC    (TP / 4)      // 1,000,000 float4 per batch row
#define GROUPS  18            // column groups
#define THREADS 256
#define STRIDE  (GROUPS * THREADS)   // 4608 float4 per sweep

__global__ void init_out_kernel(const float* __restrict__ fc1_b,
                                float* __restrict__ out) {
    out[threadIdx.x] = fc1_b[0];
}

__global__ __launch_bounds__(THREADS, 4)
void dot_kernel(const float4* __restrict__ x,
                const float4* __restrict__ W,
                const float4* __restrict__ F,
                float* __restrict__ out) {
    const int b   = blockIdx.x & (NBATCH - 1);   // batch (fastest-varying)
    const int g   = blockIdx.x >> 5;             // column group 0..17
    const int tid = threadIdx.x;

    const float4* __restrict__ xb = x + (size_t)b * NVEC;

    float a0 = 0.f, a1 = 0.f, a2 = 0.f, a3 = 0.f;

#pragma unroll 4
    for (int j = g * THREADS + tid; j < NVEC; j += STRIDE) {
        // x: read-once stream -> evict-first so it can't thrash W/F in L2
        float4 xv = __ldcs(&xb[j]);
        // W/F: shared across the 32 co-resident batch-blocks -> L2 hits
        float4 w = __ldg(&W[j]);
        float4 f = __ldg(&F[j]);
        a0 = fmaf(xv.x, fabsf(w.x) * f.x, a0);
        a1 = fmaf(xv.y, fabsf(w.y) * f.y, a1);
        a2 = fmaf(xv.z, fabsf(w.z) * f.z, a2);
        a3 = fmaf(xv.w, fabsf(w.w) * f.w, a3);
    }

    float v = (a0 + a1) + (a2 + a3);

    // ---- block reduction: warp shfl -> smem -> single atomic ----
    __shared__ float sred[THREADS / 32];
    const int lane = tid & 31;
    const int wrp  = tid >> 5;

#pragma unroll
    for (int off = 16; off; off >>= 1)
        v += __shfl_xor_sync(0xffffffffu, v, off);
    if (lane == 0) sred[wrp] = v;
    __syncthreads();

    if (wrp == 0) {
        float s = (lane < THREADS / 32) ? sred[lane] : 0.f;
#pragma unroll
        for (int off = 4; off; off >>= 1)
            s += __shfl_xor_sync(0xffffffffu, s, off);
        if (lane == 0) atomicAdd(&out[b], s);
    }
}

extern "C" void kernel_launch(void* const* d_in, const int* in_sizes, int n_in,
                              void* d_out, int out_size) {
    const float4* x  = (const float4*)d_in[0];  // [32, 4M]
    const float4* W  = (const float4*)d_in[1];  // [4M]
    const float4* F  = (const float4*)d_in[2];  // fc1_w [4M]
    const float*  bb = (const float*)d_in[3];   // fc1_b [1]
    float* out = (float*)d_out;                 // [32]

    (void)in_sizes; (void)n_in; (void)out_size;

    init_out_kernel<<<1, NBATCH>>>(bb, out);
    dot_kernel<<<NBATCH * GROUPS, THREADS>>>(x, W, F, out);
}